// round 12
// baseline (speedup 1.0000x reference)
#include <cuda_runtime.h>
#include <cuda_bf16.h>
#include <cstdint>

// GINNet on GB300. R11: single persistent megakernel. 148 co-resident CTAs
// (1/SM via 128KB smem), software grid barriers with gpu-scope fences
// (CCTL.IVALL handles cross-phase L1 staleness). Phases: setup/CSR build,
// 3x(agg -> GEMM1 -> GEMM2), readout. B staged once per GEMM phase.
// Inner bodies (mma.sync split-bf16, warp-per-node gather) proven in R7-R10.

#define NN 100000
#define NE 1600000
#define DD 128
#define NG 64
#define NCTA 148
#define NW (NCTA * 8)                    // 1184 warps
#define CH 676                           // ceil(NN / NCTA)
#define NTILE 782                        // ceil(NN / 128)
#define GM_SMEM 131072

// ---------------- device scratch (allocation-free contract) ----------------
__device__ __align__(128) float g_z[NN * DD];
__device__ __align__(128) float g_y[NN * DD];
__device__ __align__(128) float g_h[NN * DD];
__device__ __align__(128) unsigned char g_wblk[6][65536]; // W^T bf16 hi|lo swizzled
__device__ int   g_cnt[NN];
__device__ int   g_ptr[NN + 1];
__device__ int   g_cur[NN];
__device__ int   g_srcs[NE];
__device__ int   g_bsum[NCTA];
__device__ int   g_boff[NCTA];
__device__ float g_ssum[6][DD];
__device__ float g_ssq[6][DD];
__device__ float g_gsum[NG * DD];
__device__ int   g_gcnt[NG];
__device__ int   g_flags[2];
__device__ int   g_barCnt;               // NOT zeroed per run (self-resetting)
__device__ volatile int g_barGen;        // monotonic generation

// ---------------- PTX helpers ----------------
__device__ __forceinline__ uint32_t smem_u32(const void* p) {
    uint32_t a;
    asm("{ .reg .u64 t; cvta.to.shared.u64 t, %1; cvt.u32.u64 %0, t; }"
        : "=r"(a) : "l"(p));
    return a;
}
__device__ __forceinline__ void ldsm4(uint32_t* r, uint32_t addr) {
    asm volatile("ldmatrix.sync.aligned.m8n8.x4.shared.b16 {%0,%1,%2,%3}, [%4];"
                 : "=r"(r[0]), "=r"(r[1]), "=r"(r[2]), "=r"(r[3]) : "r"(addr));
}
__device__ __forceinline__ void mma16816(float* d, const uint32_t* a,
                                         const uint32_t* b) {
    asm volatile(
        "mma.sync.aligned.m16n8k16.row.col.f32.bf16.bf16.f32 "
        "{%0,%1,%2,%3}, {%4,%5,%6,%7}, {%8,%9}, {%0,%1,%2,%3};"
        : "+f"(d[0]), "+f"(d[1]), "+f"(d[2]), "+f"(d[3])
        : "r"(a[0]), "r"(a[1]), "r"(a[2]), "r"(a[3]), "r"(b[0]), "r"(b[1]));
}
__device__ __forceinline__ uint32_t pack_bf16x2(float lo, float hi) {
    __nv_bfloat16 l = __float2bfloat16(lo), h = __float2bfloat16(hi);
    return (uint32_t)__bfloat16_as_ushort(l) |
           ((uint32_t)__bfloat16_as_ushort(h) << 16);
}

// ---------------- misc helpers ----------------
__device__ __forceinline__ int get_idx(const void* p, long long i, int is64) {
    if (is64) return (int)((const long long*)p)[i];
    return ((const int*)p)[i];
}
__device__ __forceinline__ void bn_affine_block(int slot, const float* gm,
                                                const float* bt, float* sA,
                                                float* sC, int tid) {
    if (slot >= 0 && tid < DD) {
        float mean = g_ssum[slot][tid] * (1.f / NN);
        float var = g_ssq[slot][tid] * (1.f / NN) - mean * mean;
        float a = gm[tid] * rsqrtf(var + 1e-5f);
        sA[tid] = a;
        sC[tid] = bt[tid] - mean * a;
    }
}
__device__ __forceinline__ float4 act4(float4 v, float4 a, float4 c) {
    v.x = fmaxf(fmaf(v.x, a.x, c.x), 0.f);
    v.y = fmaxf(fmaf(v.y, a.y, c.y), 0.f);
    v.z = fmaxf(fmaf(v.z, a.z, c.z), 0.f);
    v.w = fmaxf(fmaf(v.w, a.w, c.w), 0.f);
    return v;
}

// Software grid barrier. All NCTA CTAs are co-resident (1 CTA/SM via smem).
// __threadfence (gpu scope) emits CCTL.IVALL -> L1 staleness handled.
__device__ __forceinline__ void gridbar() {
    __syncthreads();
    if (threadIdx.x == 0) {
        __threadfence();
        int gen = g_barGen;
        if (atomicAdd(&g_barCnt, 1) == NCTA - 1) {
            atomicExch(&g_barCnt, 0);
            __threadfence();
            g_barGen = gen + 1;
        } else {
            while (g_barGen == gen) __nanosleep(64);
        }
        __threadfence();
    }
    __syncthreads();
}

// ---------------- GEMM phase: Y = act(A) @ W, BN-stat epilogue -------------
__device__ void gemm_phase(const float* __restrict__ A, float* __restrict__ Y,
                           int wsel, int actSlot, const float* gm,
                           const float* bt, int statSlot, unsigned char* Ahi,
                           unsigned char* Alo, unsigned char* Bhi, float* cs,
                           float* cq, float* sAf, float* sCf) {
    int tid = threadIdx.x;
    int wid = tid >> 5, lane = tid & 31;
    if (tid < DD) { cs[tid] = 0.f; cq[tid] = 0.f; }
    bn_affine_block(actSlot, gm, bt, sAf, sCf, tid);
    // stage B once for all tiles of this CTA (hi|lo contiguous 64KB)
    {
        const float4* src = (const float4*)g_wblk[wsel];
        float4* dst = (float4*)Bhi;
#pragma unroll
        for (int i = 0; i < 16; i++) dst[tid + i * 256] = src[tid + i * 256];
    }
    __syncthreads();

    uint32_t aU = smem_u32(Ahi), bU = smem_u32(Bhi);
    int wrow = wid * 16;
    int arow = wrow + (lane & 15);
    int akh = (lane >> 4) & 1;
    int aswb = ((arow & 7) << 4);
    int ntp = (lane >> 4) & 1;
    int bkh = (lane >> 3) & 1;
    int brow = lane & 7;
    int bswb = (brow << 4);

    for (int tile = blockIdx.x; tile < NTILE; tile += NCTA) {
        int mBase = tile * 128;
        // stage A: 2 threads per row, act + hi/lo split + swizzled store
        {
            int r = tid >> 1, ch = tid & 1;
            int grow = mBase + r;
            bool valid = grow < NN;
            const float4* A4 = (const float4*)A;
#pragma unroll
            for (int c = 0; c < 8; c++) {
                int f4i = ch * 16 + c * 2;
                float4 v0 = make_float4(0.f, 0.f, 0.f, 0.f);
                float4 v1 = v0;
                if (valid) {
                    v0 = A4[grow * 32 + f4i];
                    v1 = A4[grow * 32 + f4i + 1];
                }
                if (actSlot >= 0 && valid) {
                    v0 = act4(v0, ((const float4*)sAf)[f4i],
                              ((const float4*)sCf)[f4i]);
                    v1 = act4(v1, ((const float4*)sAf)[f4i + 1],
                              ((const float4*)sCf)[f4i + 1]);
                }
                float f[8] = {v0.x, v0.y, v0.z, v0.w, v1.x, v1.y, v1.z, v1.w};
                uint4 hi, lo;
                uint32_t* hp = (uint32_t*)&hi;
                uint32_t* lp = (uint32_t*)&lo;
#pragma unroll
                for (int j = 0; j < 4; j++) {
                    float x0 = f[j * 2], x1 = f[j * 2 + 1];
                    __nv_bfloat16 h0 = __float2bfloat16(x0);
                    __nv_bfloat16 h1 = __float2bfloat16(x1);
                    hp[j] = (uint32_t)__bfloat16_as_ushort(h0) |
                            ((uint32_t)__bfloat16_as_ushort(h1) << 16);
                    lp[j] = pack_bf16x2(x0 - __bfloat162float(h0),
                                        x1 - __bfloat162float(h1));
                }
                int off = r * 256 + (ch * 8 + c) * 16;
                int sw = off ^ ((r & 7) << 4);
                *(uint4*)(Ahi + sw) = hi;
                *(uint4*)(Alo + sw) = lo;
            }
        }
        __syncthreads();

        float acc[16][4];
#pragma unroll
        for (int n = 0; n < 16; n++)
#pragma unroll
            for (int j = 0; j < 4; j++) acc[n][j] = 0.f;

#pragma unroll
        for (int k = 0; k < 8; k++) {
            uint32_t afH[4], afL[4];
            {
                int aoff = arow * 256 + k * 32 + akh * 16;
                ldsm4(afH, aU + (uint32_t)(aoff ^ aswb));
                ldsm4(afL, aU + 32768u + (uint32_t)(aoff ^ aswb));
            }
            uint32_t bf[32];
#pragma unroll
            for (int p = 0; p < 8; p++) {
                int boff = ((2 * p + ntp) * 8 + brow) * 256 + k * 32 + bkh * 16;
                ldsm4(&bf[p * 4], bU + (uint32_t)(boff ^ bswb));
            }
#pragma unroll
            for (int p = 0; p < 8; p++) {       // hi * hi
                mma16816(acc[2 * p], afH, &bf[4 * p]);
                mma16816(acc[2 * p + 1], afH, &bf[4 * p + 2]);
            }
#pragma unroll
            for (int p = 0; p < 8; p++) {       // lo * hi
                mma16816(acc[2 * p], afL, &bf[4 * p]);
                mma16816(acc[2 * p + 1], afL, &bf[4 * p + 2]);
            }
#pragma unroll
            for (int p = 0; p < 8; p++) {
                int boff = ((2 * p + ntp) * 8 + brow) * 256 + k * 32 + bkh * 16;
                ldsm4(&bf[p * 4], bU + 32768u + (uint32_t)(boff ^ bswb));
            }
#pragma unroll
            for (int p = 0; p < 8; p++) {       // hi * lo
                mma16816(acc[2 * p], afH, &bf[4 * p]);
                mma16816(acc[2 * p + 1], afH, &bf[4 * p + 2]);
            }
        }

        // epilogue
        int r0 = mBase + wrow + (lane >> 2);
        int r1 = r0 + 8;
#pragma unroll
        for (int n = 0; n < 16; n++) {
            int col = n * 8 + 2 * (lane & 3);
            if (r0 < NN)
                *(float2*)&Y[r0 * DD + col] = make_float2(acc[n][0], acc[n][1]);
            if (r1 < NN)
                *(float2*)&Y[r1 * DD + col] = make_float2(acc[n][2], acc[n][3]);
            float s0 = acc[n][0] + acc[n][2];
            float s1 = acc[n][1] + acc[n][3];
            float q0 = acc[n][0] * acc[n][0] + acc[n][2] * acc[n][2];
            float q1 = acc[n][1] * acc[n][1] + acc[n][3] * acc[n][3];
#pragma unroll
            for (int o = 4; o <= 16; o <<= 1) {
                s0 += __shfl_xor_sync(0xffffffffu, s0, o);
                s1 += __shfl_xor_sync(0xffffffffu, s1, o);
                q0 += __shfl_xor_sync(0xffffffffu, q0, o);
                q1 += __shfl_xor_sync(0xffffffffu, q1, o);
            }
            if (lane < 4) {
                int c2 = n * 8 + 2 * lane;
                atomicAdd(&cs[c2], s0);
                atomicAdd(&cs[c2 + 1], s1);
                atomicAdd(&cq[c2], q0);
                atomicAdd(&cq[c2 + 1], q1);
            }
        }
        __syncthreads();    // protect Ahi/Alo before next tile's restage
    }
    if (tid < DD) {
        atomicAdd(&g_ssum[statSlot][tid], cs[tid]);
        atomicAdd(&g_ssq[statSlot][tid], cq[tid]);
    }
}

// ---------------- the megakernel ----------------
__global__ __launch_bounds__(256, 1)
void k_mega(const float* __restrict__ x, const void* ei, const void* bt,
            const float* __restrict__ W1, const float* __restrict__ g1,
            const float* __restrict__ b1, const float* __restrict__ W2,
            const float* __restrict__ g2, const float* __restrict__ b2,
            const float* __restrict__ eps, float* __restrict__ out) {
    extern __shared__ unsigned char dyn[];
    __shared__ float cs[DD], cq[DD];
    __shared__ __align__(16) float sAf[DD], sCf[DD];
    __shared__ int ish[256];
    __shared__ int wred[8];
    __shared__ float red[4];
    unsigned char* Ahi = dyn;
    unsigned char* Alo = dyn + 32768;
    unsigned char* Bhi = dyn + 65536;

    int cta = blockIdx.x;
    int tid = threadIdx.x;
    int wid = tid >> 5, lane = tid & 31;
    int gid = cta * 256 + tid;
    const int gstride = NCTA * 256;

    // ---- P0: zero + wprep + detect ----
    for (int i = gid; i < NN; i += gstride) {
        g_cnt[i] = 0;
        if (i < 6 * DD) { ((float*)g_ssum)[i] = 0.f; ((float*)g_ssq)[i] = 0.f; }
        if (i < NG * DD) g_gsum[i] = 0.f;
        if (i < NG) g_gcnt[i] = 0;
        if (i < 6 * DD * DD) {
            int m = i >> 14;
            int r = i & 16383;
            int n = r >> 7, k = r & 127;
            int l = m >> 1;
            const float* W = (m & 1) ? (W2 + l * DD * DD) : (W1 + l * DD * DD);
            float v = W[k * DD + n];
            __nv_bfloat16 h = __float2bfloat16(v);
            __nv_bfloat16 lo = __float2bfloat16(v - __bfloat162float(h));
            int off = n * 256 + k * 2;
            int sw = off ^ ((n & 7) << 4);
            *(__nv_bfloat16*)(g_wblk[m] + sw) = h;
            *(__nv_bfloat16*)(g_wblk[m] + 32768 + sw) = lo;
        }
    }
    if (cta == 0) {
        if (tid < 2) ish[tid] = 0;
        __syncthreads();
        const long long* pe = (const long long*)ei;
        const long long* pb = (const long long*)bt;
        for (int j = tid; j < 4096; j += 256) {
            long long v = pe[(long long)j * 390];
            if (v < 0 || v >= NN) atomicOr(&ish[0], 1);
            long long w = pb[(long long)j * 12];
            if (w < 0 || w >= NG) atomicOr(&ish[1], 1);
        }
        __syncthreads();
        if (tid == 0) {
            g_flags[0] = ish[0] ? 0 : 1;
            g_flags[1] = ish[1] ? 0 : 1;
        }
    }
    gridbar();
    int isE = g_flags[0], isB = g_flags[1];

    // ---- P1: count ----
    for (int e = gid; e < NE; e += gstride) {
        int t = get_idx(ei, (long long)NE + e, isE);
        atomicAdd(&g_cnt[t], 1);
    }
    gridbar();

    // ---- P2a: per-CTA chunk sums ----
    {
        int base = cta * CH, end = min(base + CH, NN);
        int s = 0;
        for (int i = base + tid; i < end; i += 256) s += g_cnt[i];
#pragma unroll
        for (int o = 16; o > 0; o >>= 1) s += __shfl_xor_sync(0xffffffffu, s, o);
        if (lane == 0) wred[wid] = s;
        __syncthreads();
        if (tid == 0) {
            int t = 0;
#pragma unroll
            for (int w = 0; w < 8; w++) t += wred[w];
            g_bsum[cta] = t;
        }
    }
    gridbar();

    // ---- P2b: CTA0 scans the 148 partials ----
    if (cta == 0) {
        int v = (tid < NCTA) ? g_bsum[tid] : 0;
        ish[tid] = v;
        __syncthreads();
#pragma unroll
        for (int off = 1; off < 256; off <<= 1) {
            int u = (tid >= off) ? ish[tid - off] : 0;
            __syncthreads();
            ish[tid] += u;
            __syncthreads();
        }
        if (tid < NCTA) g_boff[tid] = ish[tid] - v;   // exclusive
    }
    gridbar();

    // ---- P2c: per-CTA exclusive scan of its chunk -> g_ptr/g_cur ----
    {
        int base = cta * CH, end = min(base + CH, NN);
        int i0 = base + tid * 3;
        int c0 = (i0 < end) ? g_cnt[i0] : 0;
        int c1 = (i0 + 1 < end) ? g_cnt[i0 + 1] : 0;
        int c2 = (i0 + 2 < end) ? g_cnt[i0 + 2] : 0;
        int tsum = c0 + c1 + c2;
        int incl = tsum;
#pragma unroll
        for (int o = 1; o < 32; o <<= 1) {
            int v = __shfl_up_sync(0xffffffffu, incl, o);
            if (lane >= o) incl += v;
        }
        if (lane == 31) wred[wid] = incl;
        __syncthreads();
        if (tid == 0) {
            int run = 0;
#pragma unroll
            for (int w = 0; w < 8; w++) { int v = wred[w]; wred[w] = run; run += v; }
        }
        __syncthreads();
        int p = g_boff[cta] + wred[wid] + (incl - tsum);
        if (i0 < end) {
            g_ptr[i0] = p; g_cur[i0] = p; p += c0;
            if (i0 == NN - 1) g_ptr[NN] = p;
        }
        if (i0 + 1 < end) {
            g_ptr[i0 + 1] = p; g_cur[i0 + 1] = p; p += c1;
            if (i0 + 1 == NN - 1) g_ptr[NN] = p;
        }
        if (i0 + 2 < end) {
            g_ptr[i0 + 2] = p; g_cur[i0 + 2] = p; p += c2;
            if (i0 + 2 == NN - 1) g_ptr[NN] = p;
        }
    }
    gridbar();

    // ---- P3: fill ----
    for (int e = gid; e < NE; e += gstride) {
        int s = get_idx(ei, e, isE);
        int t = get_idx(ei, (long long)NE + e, isE);
        int pos = atomicAdd(&g_cur[t], 1);
        g_srcs[pos] = s;
    }
    gridbar();

    // ---- P4: layers ----
    for (int l = 0; l < 3; l++) {
        // agg: z = (1+eps)*act(h) + sum_neighbors act(h)
        int slot = 2 * l - 1;
        const float* gmP = (l == 0) ? g1 : (g2 + (l - 1) * DD);
        const float* btP = (l == 0) ? b1 : (b2 + (l - 1) * DD);
        bn_affine_block(slot, gmP, btP, sAf, sCf, tid);
        __syncthreads();
        {
            const float4* hin = (l == 0) ? (const float4*)x : (const float4*)g_h;
            float4 ca = make_float4(1.f, 1.f, 1.f, 1.f);
            float4 cc = make_float4(0.f, 0.f, 0.f, 0.f);
            if (slot >= 0) {
                ca = ((const float4*)sAf)[lane];
                cc = ((const float4*)sCf)[lane];
            }
            float epsl = 1.f + eps[l];
            for (int node = cta * 8 + wid; node < NN; node += NW) {
                int beg = g_ptr[node], end = g_ptr[node + 1];
                float4 v = hin[node * 32 + lane];
                if (slot >= 0) v = act4(v, ca, cc);
                float4 acc = make_float4(v.x * epsl, v.y * epsl, v.z * epsl,
                                         v.w * epsl);
                int e = beg;
                for (; e + 4 <= end; e += 4) {
                    int s0 = __ldg(&g_srcs[e]);
                    int s1 = __ldg(&g_srcs[e + 1]);
                    int s2 = __ldg(&g_srcs[e + 2]);
                    int s3 = __ldg(&g_srcs[e + 3]);
                    float4 u0 = hin[s0 * 32 + lane];
                    float4 u1 = hin[s1 * 32 + lane];
                    float4 u2 = hin[s2 * 32 + lane];
                    float4 u3 = hin[s3 * 32 + lane];
                    if (slot >= 0) {
                        u0 = act4(u0, ca, cc); u1 = act4(u1, ca, cc);
                        u2 = act4(u2, ca, cc); u3 = act4(u3, ca, cc);
                    }
                    acc.x += (u0.x + u1.x) + (u2.x + u3.x);
                    acc.y += (u0.y + u1.y) + (u2.y + u3.y);
                    acc.z += (u0.z + u1.z) + (u2.z + u3.z);
                    acc.w += (u0.w + u1.w) + (u2.w + u3.w);
                }
                for (; e < end; e++) {
                    int s = __ldg(&g_srcs[e]);
                    float4 u = hin[s * 32 + lane];
                    if (slot >= 0) u = act4(u, ca, cc);
                    acc.x += u.x; acc.y += u.y; acc.z += u.z; acc.w += u.w;
                }
                ((float4*)g_z)[node * 32 + lane] = acc;
            }
        }
        gridbar();
        // GEMM1: y = z @ W1[l]  (no act), stats slot 2l
        gemm_phase(g_z, g_y, 2 * l, -1, nullptr, nullptr, 2 * l, Ahi, Alo, Bhi,
                   cs, cq, sAf, sCf);
        gridbar();
        // GEMM2: h = act_{2l}(y) @ W2[l], stats slot 2l+1
        gemm_phase(g_y, g_h, 2 * l + 1, 2 * l, g1 + l * DD, b1 + l * DD,
                   2 * l + 1, Ahi, Alo, Bhi, cs, cq, sAf, sCf);
        gridbar();
    }

    // ---- P5: node embeddings (act slot 5) ----
    bn_affine_block(5, g2 + 2 * DD, b2 + 2 * DD, sAf, sCf, tid);
    __syncthreads();
    for (int i = gid; i < NN * 32; i += gstride) {
        int c4 = i & 31;
        float4 v = ((const float4*)g_h)[i];
        v = act4(v, ((const float4*)sAf)[c4], ((const float4*)sCf)[c4]);
        ((float4*)out)[i] = v;
    }
    gridbar();

    // ---- P6: graph sums (run-length over sorted batch) ----
    {
        int proc = cta * 2 + (tid >> 7);
        int d = tid & 127;
        for (int chk = proc; chk * 256 < NN; chk += 2 * NCTA) {
            int beg = chk * 256;
            int end = min(beg + 256, NN);
            int cur = get_idx(bt, beg, isB);
            int runStart = beg;
            float acc = 0.f;
            for (int i = beg; i < end; i++) {
                int b = get_idx(bt, i, isB);
                if (b != cur) {
                    atomicAdd(&g_gsum[cur * DD + d], acc);
                    if (d == 0) atomicAdd(&g_gcnt[cur], i - runStart);
                    acc = 0.f; cur = b; runStart = i;
                }
                acc += out[i * DD + d];
            }
            atomicAdd(&g_gsum[cur * DD + d], acc);
            if (d == 0) atomicAdd(&g_gcnt[cur], end - runStart);
        }
    }
    gridbar();

    // ---- P7: normalized graph embeddings ----
    if (cta < NG) {
        float v = 0.f, s = 0.f;
        if (tid < DD) {
            float cnt = (float)g_gcnt[cta];
            v = g_gsum[cta * DD + tid] / fmaxf(cnt, 1.f);
            s = v * v;
        }
#pragma unroll
        for (int o = 16; o > 0; o >>= 1) s += __shfl_xor_sync(0xffffffffu, s, o);
        if (lane == 0 && wid < 4) red[wid] = s;
        __syncthreads();
        float tot = red[0] + red[1] + red[2] + red[3];
        if (tid < DD)
            out[NN * DD + cta * DD + tid] = v / fmaxf(sqrtf(tot), 1e-12f);
    }
}

// ---------------- launch ----------------
extern "C" void kernel_launch(void* const* d_in, const int* in_sizes, int n_in,
                              void* d_out, int out_size) {
    const float* x  = (const float*)d_in[0];
    const void*  ei = d_in[1];
    const void*  bt = d_in[2];
    const float* W1 = (const float*)d_in[3];
    const float* g1 = (const float*)d_in[4];
    const float* b1 = (const float*)d_in[5];
    const float* W2 = (const float*)d_in[6];
    const float* g2 = (const float*)d_in[7];
    const float* b2 = (const float*)d_in[8];
    const float* eps = (const float*)d_in[9];
    float* out = (float*)d_out;
    (void)in_sizes; (void)n_in; (void)out_size;

    cudaFuncSetAttribute(k_mega, cudaFuncAttributeMaxDynamicSharedMemorySize,
                         GM_SMEM);
    k_mega<<<NCTA, 256, GM_SMEM>>>(x, ei, bt, W1, g1, b1, W2, g2, b2, eps, out);
}

// round 13
// speedup vs baseline: 1.6211x; 1.6211x over previous
#include <cuda_runtime.h>
#include <cuda_bf16.h>
#include <cstdint>

// GINNet on GB300. R12: megakernel REVERTED (occupancy starvation killed the
// agg phase: 12.5% occ -> 1335us). Back to R10 split kernels, keeping the one
// good megakernel idea: PERSISTENT GEMM (148 CTAs loop over tiles, W staged
// once per kernel instead of once per tile-CTA).

#define NN 100000
#define NE 1600000
#define DD 128
#define NG 64

#define SCAN_CHUNK 1024
#define SCAN_NB ((NN + SCAN_CHUNK - 1) / SCAN_CHUNK)   // 98

#define NCTA 148
#define NTILE ((NN + 127) / 128)                        // 782
#define GM_SMEM 131072

// ---------------- device scratch (allocation-free contract) ----------------
__device__ __align__(128) float g_z[NN * DD];
__device__ __align__(128) float g_y[NN * DD];
__device__ __align__(128) float g_h[NN * DD];
__device__ __align__(128) unsigned char g_wblk[6][65536]; // W^T bf16 hi|lo swizzled
__device__ int   g_cnt[NN];
__device__ int   g_ptr[NN + 1];
__device__ int   g_cur[NN];
__device__ int   g_srcs[NE];
__device__ int   g_bsum[SCAN_NB];
__device__ int   g_boff[SCAN_NB];
__device__ float g_ssum[6][DD];
__device__ float g_ssq[6][DD];
__device__ float g_gsum[NG * DD];
__device__ int   g_gcnt[NG];
__device__ int   g_flags[2];

// ---------------- PTX helpers ----------------
__device__ __forceinline__ uint32_t smem_u32(const void* p) {
    uint32_t a;
    asm("{ .reg .u64 t; cvta.to.shared.u64 t, %1; cvt.u32.u64 %0, t; }"
        : "=r"(a) : "l"(p));
    return a;
}
__device__ __forceinline__ void ldsm4(uint32_t* r, uint32_t addr) {
    asm volatile("ldmatrix.sync.aligned.m8n8.x4.shared.b16 {%0,%1,%2,%3}, [%4];"
                 : "=r"(r[0]), "=r"(r[1]), "=r"(r[2]), "=r"(r[3]) : "r"(addr));
}
__device__ __forceinline__ void mma16816(float* d, const uint32_t* a,
                                         const uint32_t* b) {
    asm volatile(
        "mma.sync.aligned.m16n8k16.row.col.f32.bf16.bf16.f32 "
        "{%0,%1,%2,%3}, {%4,%5,%6,%7}, {%8,%9}, {%0,%1,%2,%3};"
        : "+f"(d[0]), "+f"(d[1]), "+f"(d[2]), "+f"(d[3])
        : "r"(a[0]), "r"(a[1]), "r"(a[2]), "r"(a[3]), "r"(b[0]), "r"(b[1]));
}
__device__ __forceinline__ uint32_t pack_bf16x2(float lo, float hi) {
    __nv_bfloat16 l = __float2bfloat16(lo), h = __float2bfloat16(hi);
    return (uint32_t)__bfloat16_as_ushort(l) |
           ((uint32_t)__bfloat16_as_ushort(h) << 16);
}

// ---------------- misc helpers ----------------
__device__ __forceinline__ int get_idx(const void* p, long long i, int is64) {
    if (is64) return (int)((const long long*)p)[i];
    return ((const int*)p)[i];
}
__device__ __forceinline__ void bn_affine_block(int slot, const float* gm,
                                                const float* bt, float* sA,
                                                float* sC, int tid) {
    if (slot >= 0 && tid < DD) {
        float mean = g_ssum[slot][tid] * (1.f / NN);
        float var = g_ssq[slot][tid] * (1.f / NN) - mean * mean;
        float a = gm[tid] * rsqrtf(var + 1e-5f);
        sA[tid] = a;
        sC[tid] = bt[tid] - mean * a;
    }
}
__device__ __forceinline__ float4 act4(float4 v, float4 a, float4 c) {
    v.x = fmaxf(fmaf(v.x, a.x, c.x), 0.f);
    v.y = fmaxf(fmaf(v.y, a.y, c.y), 0.f);
    v.z = fmaxf(fmaf(v.z, a.z, c.z), 0.f);
    v.w = fmaxf(fmaf(v.w, a.w, c.w), 0.f);
    return v;
}

// ---------------- merged setup: zero + detect + wprep ----------------
__global__ void k_setup(const void* ei, const void* bt,
                        const float* __restrict__ W1,
                        const float* __restrict__ W2) {
    int i = blockIdx.x * blockDim.x + threadIdx.x;
    if (i < NN) g_cnt[i] = 0;
    if (i < 6 * DD) { ((float*)g_ssum)[i] = 0.f; ((float*)g_ssq)[i] = 0.f; }
    if (i < NG * DD) g_gsum[i] = 0.f;
    if (i < NG) g_gcnt[i] = 0;
    if (i < 6 * DD * DD) {
        int m = i >> 14;
        int r = i & 16383;
        int n = r >> 7, k = r & 127;
        int l = m >> 1;
        const float* W = (m & 1) ? (W2 + l * DD * DD) : (W1 + l * DD * DD);
        float v = W[k * DD + n];
        __nv_bfloat16 h = __float2bfloat16(v);
        __nv_bfloat16 lo = __float2bfloat16(v - __bfloat162float(h));
        int off = n * 256 + k * 2;
        int sw = off ^ ((n & 7) << 4);
        *(__nv_bfloat16*)(g_wblk[m] + sw) = h;
        *(__nv_bfloat16*)(g_wblk[m] + 32768 + sw) = lo;
    }
    if (blockIdx.x == 0) {
        __shared__ int bad[2];
        if (threadIdx.x < 2) bad[threadIdx.x] = 0;
        __syncthreads();
        const long long* pe = (const long long*)ei;
        const long long* pb = (const long long*)bt;
        for (int j = threadIdx.x; j < 4096; j += blockDim.x) {
            long long v = pe[(long long)j * 390];
            if (v < 0 || v >= NN) atomicOr(&bad[0], 1);
            long long w = pb[(long long)j * 12];
            if (w < 0 || w >= NG) atomicOr(&bad[1], 1);
        }
        __syncthreads();
        if (threadIdx.x == 0) {
            g_flags[0] = bad[0] ? 0 : 1;
            g_flags[1] = bad[1] ? 0 : 1;
        }
    }
}

__global__ void k_count(const void* ei) {
    int e = blockIdx.x * blockDim.x + threadIdx.x;
    if (e >= NE) return;
    int t = get_idx(ei, (long long)NE + e, g_flags[0]);
    atomicAdd(&g_cnt[t], 1);
}

__global__ void k_scanA() {
    __shared__ int wsum[8];
    int b = blockIdx.x, tid = threadIdx.x;
    int base = b * SCAN_CHUNK + tid * 4;
    int s = 0;
#pragma unroll
    for (int j = 0; j < 4; j++) { int i = base + j; if (i < NN) s += g_cnt[i]; }
#pragma unroll
    for (int o = 16; o > 0; o >>= 1) s += __shfl_xor_sync(0xffffffffu, s, o);
    if ((tid & 31) == 0) wsum[tid >> 5] = s;
    __syncthreads();
    if (tid == 0) {
        int t = 0;
#pragma unroll
        for (int w = 0; w < 8; w++) t += wsum[w];
        g_bsum[b] = t;
    }
}

__global__ void k_scanB() {
    __shared__ int sh[128];
    int t = threadIdx.x;
    sh[t] = (t < SCAN_NB) ? g_bsum[t] : 0;
    __syncthreads();
#pragma unroll
    for (int off = 1; off < 128; off <<= 1) {
        int v = (t >= off) ? sh[t - off] : 0;
        __syncthreads();
        sh[t] += v;
        __syncthreads();
    }
    if (t < SCAN_NB) g_boff[t] = (t == 0) ? 0 : sh[t - 1];
}

__global__ void k_scanC() {
    __shared__ int wexc[8];
    int b = blockIdx.x, tid = threadIdx.x;
    int lane = tid & 31, wid = tid >> 5;
    int base = b * SCAN_CHUNK + tid * 4;
    int c[4];
    int tsum = 0;
#pragma unroll
    for (int j = 0; j < 4; j++) {
        int i = base + j;
        c[j] = (i < NN) ? g_cnt[i] : 0;
        tsum += c[j];
    }
    int incl = tsum;
#pragma unroll
    for (int o = 1; o < 32; o <<= 1) {
        int v = __shfl_up_sync(0xffffffffu, incl, o);
        if (lane >= o) incl += v;
    }
    if (lane == 31) wexc[wid] = incl;
    __syncthreads();
    if (tid == 0) {
        int run = 0;
#pragma unroll
        for (int w = 0; w < 8; w++) { int v = wexc[w]; wexc[w] = run; run += v; }
    }
    __syncthreads();
    int p = g_boff[b] + wexc[wid] + (incl - tsum);
#pragma unroll
    for (int j = 0; j < 4; j++) {
        int i = base + j;
        if (i < NN) {
            g_ptr[i] = p; g_cur[i] = p; p += c[j];
            if (i == NN - 1) g_ptr[NN] = p;
        }
    }
}

__global__ void k_fill(const void* ei) {
    int e = blockIdx.x * blockDim.x + threadIdx.x;
    if (e >= NE) return;
    int is64 = g_flags[0];
    int s = get_idx(ei, e, is64);
    int t = get_idx(ei, (long long)NE + e, is64);
    int pos = atomicAdd(&g_cur[t], 1);
    g_srcs[pos] = s;
}

// ---------------- aggregation: warp per node, x4-unrolled edge loop --------
__global__ void k_agg(const float* __restrict__ x, int useX, int slot,
                      const float* __restrict__ gm, const float* __restrict__ bt,
                      const float* __restrict__ epsArr, int layer) {
    __shared__ __align__(16) float sAf[DD], sCf[DD];
    int tid = threadIdx.x;
    bn_affine_block(slot, gm, bt, sAf, sCf, tid);
    __syncthreads();

    int gt = blockIdx.x * blockDim.x + tid;
    int node = gt >> 5;
    int lane = gt & 31;
    if (node >= NN) return;
    const float4* hin = useX ? (const float4*)x : (const float4*)g_h;
    float4 ca = make_float4(1.f, 1.f, 1.f, 1.f);
    float4 cc = make_float4(0.f, 0.f, 0.f, 0.f);
    if (slot >= 0) {
        ca = ((const float4*)sAf)[lane];
        cc = ((const float4*)sCf)[lane];
    }
    float epsl = 1.f + epsArr[layer];
    int beg = g_ptr[node], end = g_ptr[node + 1];
    float4 v = hin[node * 32 + lane];
    if (slot >= 0) v = act4(v, ca, cc);
    float4 acc = make_float4(v.x * epsl, v.y * epsl, v.z * epsl, v.w * epsl);

    int e = beg;
    for (; e + 4 <= end; e += 4) {
        int s0 = __ldg(&g_srcs[e]);
        int s1 = __ldg(&g_srcs[e + 1]);
        int s2 = __ldg(&g_srcs[e + 2]);
        int s3 = __ldg(&g_srcs[e + 3]);
        float4 u0 = hin[s0 * 32 + lane];
        float4 u1 = hin[s1 * 32 + lane];
        float4 u2 = hin[s2 * 32 + lane];
        float4 u3 = hin[s3 * 32 + lane];
        if (slot >= 0) {
            u0 = act4(u0, ca, cc); u1 = act4(u1, ca, cc);
            u2 = act4(u2, ca, cc); u3 = act4(u3, ca, cc);
        }
        acc.x += (u0.x + u1.x) + (u2.x + u3.x);
        acc.y += (u0.y + u1.y) + (u2.y + u3.y);
        acc.z += (u0.z + u1.z) + (u2.z + u3.z);
        acc.w += (u0.w + u1.w) + (u2.w + u3.w);
    }
    for (; e < end; e++) {
        int s = __ldg(&g_srcs[e]);
        float4 u = hin[s * 32 + lane];
        if (slot >= 0) u = act4(u, ca, cc);
        acc.x += u.x; acc.y += u.y; acc.z += u.z; acc.w += u.w;
    }
    ((float4*)g_z)[node * 32 + lane] = acc;
}

// ---------------- PERSISTENT mma.sync GEMM: Y = act(A) @ W ------------------
// 148 CTAs, each loops over ~5.3 tiles. B staged ONCE per kernel. BN stats
// accumulated in smem across tiles; one global atomic at the end.
__global__ __launch_bounds__(256, 1)
void k_gemmP(int srcSel, int dstSel, const float* __restrict__ gm,
             const float* __restrict__ bt, int actSlot, int statSlot, int wsel) {
    extern __shared__ unsigned char dyn[];
    __shared__ float cs[DD], cq[DD];
    __shared__ __align__(16) float sAf[DD], sCf[DD];
    unsigned char* Ahi = dyn;
    unsigned char* Alo = dyn + 32768;
    unsigned char* Bhi = dyn + 65536;

    int tid = threadIdx.x;
    int wid = tid >> 5, lane = tid & 31;
    const float* A = srcSel ? g_y : g_z;
    float* Y = dstSel ? g_h : g_y;

    if (tid < DD) { cs[tid] = 0.f; cq[tid] = 0.f; }
    bn_affine_block(actSlot, gm, bt, sAf, sCf, tid);
    // stage B once (hi|lo contiguous 64KB)
    {
        const float4* src = (const float4*)g_wblk[wsel];
        float4* dst = (float4*)Bhi;
#pragma unroll
        for (int i = 0; i < 16; i++) dst[tid + i * 256] = src[tid + i * 256];
    }
    __syncthreads();

    uint32_t aU = smem_u32(Ahi), bU = smem_u32(Bhi);
    int wrow = wid * 16;
    int arow = wrow + (lane & 15);
    int akh = (lane >> 4) & 1;
    int aswb = ((arow & 7) << 4);
    int ntp = (lane >> 4) & 1;
    int bkh = (lane >> 3) & 1;
    int brow = lane & 7;
    int bswb = (brow << 4);

    for (int tile = blockIdx.x; tile < NTILE; tile += NCTA) {
        int mBase = tile * 128;
        // stage A: 2 threads per row, act + hi/lo split + swizzled store
        {
            int r = tid >> 1, ch = tid & 1;
            int grow = mBase + r;
            bool valid = grow < NN;
            const float4* A4 = (const float4*)A;
#pragma unroll
            for (int c = 0; c < 8; c++) {
                int f4i = ch * 16 + c * 2;
                float4 v0 = make_float4(0.f, 0.f, 0.f, 0.f);
                float4 v1 = v0;
                if (valid) {
                    v0 = A4[grow * 32 + f4i];
                    v1 = A4[grow * 32 + f4i + 1];
                }
                if (actSlot >= 0 && valid) {
                    v0 = act4(v0, ((const float4*)sAf)[f4i],
                              ((const float4*)sCf)[f4i]);
                    v1 = act4(v1, ((const float4*)sAf)[f4i + 1],
                              ((const float4*)sCf)[f4i + 1]);
                }
                float f[8] = {v0.x, v0.y, v0.z, v0.w, v1.x, v1.y, v1.z, v1.w};
                uint4 hi, lo;
                uint32_t* hp = (uint32_t*)&hi;
                uint32_t* lp = (uint32_t*)&lo;
#pragma unroll
                for (int j = 0; j < 4; j++) {
                    float x0 = f[j * 2], x1 = f[j * 2 + 1];
                    __nv_bfloat16 h0 = __float2bfloat16(x0);
                    __nv_bfloat16 h1 = __float2bfloat16(x1);
                    hp[j] = (uint32_t)__bfloat16_as_ushort(h0) |
                            ((uint32_t)__bfloat16_as_ushort(h1) << 16);
                    lp[j] = pack_bf16x2(x0 - __bfloat162float(h0),
                                        x1 - __bfloat162float(h1));
                }
                int off = r * 256 + (ch * 8 + c) * 16;
                int sw = off ^ ((r & 7) << 4);
                *(uint4*)(Ahi + sw) = hi;
                *(uint4*)(Alo + sw) = lo;
            }
        }
        __syncthreads();

        float acc[16][4];
#pragma unroll
        for (int n = 0; n < 16; n++)
#pragma unroll
            for (int j = 0; j < 4; j++) acc[n][j] = 0.f;

#pragma unroll
        for (int k = 0; k < 8; k++) {
            uint32_t afH[4], afL[4];
            {
                int aoff = arow * 256 + k * 32 + akh * 16;
                ldsm4(afH, aU + (uint32_t)(aoff ^ aswb));
                ldsm4(afL, aU + 32768u + (uint32_t)(aoff ^ aswb));
            }
            uint32_t bf[32];
#pragma unroll
            for (int p = 0; p < 8; p++) {
                int boff = ((2 * p + ntp) * 8 + brow) * 256 + k * 32 + bkh * 16;
                ldsm4(&bf[p * 4], bU + (uint32_t)(boff ^ bswb));
            }
#pragma unroll
            for (int p = 0; p < 8; p++) {       // hi * hi
                mma16816(acc[2 * p], afH, &bf[4 * p]);
                mma16816(acc[2 * p + 1], afH, &bf[4 * p + 2]);
            }
#pragma unroll
            for (int p = 0; p < 8; p++) {       // lo * hi
                mma16816(acc[2 * p], afL, &bf[4 * p]);
                mma16816(acc[2 * p + 1], afL, &bf[4 * p + 2]);
            }
#pragma unroll
            for (int p = 0; p < 8; p++) {
                int boff = ((2 * p + ntp) * 8 + brow) * 256 + k * 32 + bkh * 16;
                ldsm4(&bf[p * 4], bU + 32768u + (uint32_t)(boff ^ bswb));
            }
#pragma unroll
            for (int p = 0; p < 8; p++) {       // hi * lo
                mma16816(acc[2 * p], afH, &bf[4 * p]);
                mma16816(acc[2 * p + 1], afH, &bf[4 * p + 2]);
            }
        }

        // epilogue
        int r0 = mBase + wrow + (lane >> 2);
        int r1 = r0 + 8;
#pragma unroll
        for (int n = 0; n < 16; n++) {
            int col = n * 8 + 2 * (lane & 3);
            if (r0 < NN)
                *(float2*)&Y[r0 * DD + col] = make_float2(acc[n][0], acc[n][1]);
            if (r1 < NN)
                *(float2*)&Y[r1 * DD + col] = make_float2(acc[n][2], acc[n][3]);
            float s0 = acc[n][0] + acc[n][2];
            float s1 = acc[n][1] + acc[n][3];
            float q0 = acc[n][0] * acc[n][0] + acc[n][2] * acc[n][2];
            float q1 = acc[n][1] * acc[n][1] + acc[n][3] * acc[n][3];
#pragma unroll
            for (int o = 4; o <= 16; o <<= 1) {
                s0 += __shfl_xor_sync(0xffffffffu, s0, o);
                s1 += __shfl_xor_sync(0xffffffffu, s1, o);
                q0 += __shfl_xor_sync(0xffffffffu, q0, o);
                q1 += __shfl_xor_sync(0xffffffffu, q1, o);
            }
            if (lane < 4) {
                int c2 = n * 8 + 2 * lane;
                atomicAdd(&cs[c2], s0);
                atomicAdd(&cs[c2 + 1], s1);
                atomicAdd(&cq[c2], q0);
                atomicAdd(&cq[c2 + 1], q1);
            }
        }
        __syncthreads();    // protect Ahi/Alo before next tile's restage
    }
    if (tid < DD) {
        atomicAdd(&g_ssum[statSlot][tid], cs[tid]);
        atomicAdd(&g_ssq[statSlot][tid], cq[tid]);
    }
}

// ---------------- readout ----------------
__global__ void k_nodeemb(float* __restrict__ out, const float* __restrict__ gm,
                          const float* __restrict__ bt) {
    __shared__ __align__(16) float sAf[DD], sCf[DD];
    int tid = threadIdx.x;
    bn_affine_block(5, gm, bt, sAf, sCf, tid);
    __syncthreads();
    int i = blockIdx.x * blockDim.x + tid;
    if (i >= NN * 32) return;
    int c4 = i & 31;
    float4 v = ((const float4*)g_h)[i];
    v = act4(v, ((const float4*)sAf)[c4], ((const float4*)sCf)[c4]);
    ((float4*)out)[i] = v;
}

__global__ void k_gsum(const float* __restrict__ emb, const void* bt) {
    int d = threadIdx.x;
    int beg = blockIdx.x * 256;
    int end = min(beg + 256, NN);
    if (beg >= NN) return;
    int is64 = g_flags[1];
    int cur = get_idx(bt, beg, is64);
    int runStart = beg;
    float acc = 0.f;
    for (int i = beg; i < end; i++) {
        int b = get_idx(bt, i, is64);
        if (b != cur) {
            atomicAdd(&g_gsum[cur * DD + d], acc);
            if (d == 0) atomicAdd(&g_gcnt[cur], i - runStart);
            acc = 0.f; cur = b; runStart = i;
        }
        acc += emb[i * DD + d];
    }
    atomicAdd(&g_gsum[cur * DD + d], acc);
    if (d == 0) atomicAdd(&g_gcnt[cur], end - runStart);
}

__global__ void k_gemb(float* __restrict__ out) {
    int g = blockIdx.x, d = threadIdx.x;
    float cnt = (float)g_gcnt[g];
    float v = g_gsum[g * DD + d] / fmaxf(cnt, 1.f);
    float s = v * v;
#pragma unroll
    for (int o = 16; o > 0; o >>= 1) s += __shfl_xor_sync(0xffffffffu, s, o);
    __shared__ float red[4];
    if ((d & 31) == 0) red[d >> 5] = s;
    __syncthreads();
    float tot = red[0] + red[1] + red[2] + red[3];
    float nrm = fmaxf(sqrtf(tot), 1e-12f);
    out[NN * DD + g * DD + d] = v / nrm;
}

// ---------------- launch ----------------
extern "C" void kernel_launch(void* const* d_in, const int* in_sizes, int n_in,
                              void* d_out, int out_size) {
    const float* x  = (const float*)d_in[0];
    const void*  ei = d_in[1];
    const void*  bt = d_in[2];
    const float* W1 = (const float*)d_in[3];
    const float* g1 = (const float*)d_in[4];
    const float* b1 = (const float*)d_in[5];
    const float* W2 = (const float*)d_in[6];
    const float* g2 = (const float*)d_in[7];
    const float* b2 = (const float*)d_in[8];
    const float* eps = (const float*)d_in[9];
    float* out = (float*)d_out;
    (void)in_sizes; (void)n_in; (void)out_size;

    cudaFuncSetAttribute(k_gemmP, cudaFuncAttributeMaxDynamicSharedMemorySize,
                         GM_SMEM);

    k_setup<<<(NN + 255) / 256, 256>>>(ei, bt, W1, W2);
    k_count<<<(NE + 255) / 256, 256>>>(ei);
    k_scanA<<<SCAN_NB, 256>>>();
    k_scanB<<<1, 128>>>();
    k_scanC<<<SCAN_NB, 256>>>();
    k_fill<<<(NE + 255) / 256, 256>>>(ei);

    for (int l = 0; l < 3; l++) {
        int sPrev = 2 * l - 1;
        const float* gmP = (l == 0) ? g1 : (g2 + (l - 1) * DD);
        const float* btP = (l == 0) ? b1 : (b2 + (l - 1) * DD);
        k_agg<<<(NN * 32 + 255) / 256, 256>>>(x, l == 0 ? 1 : 0,
                                              l == 0 ? -1 : sPrev, gmP, btP,
                                              eps, l);
        k_gemmP<<<NCTA, 256, GM_SMEM>>>(0, 0, g1, b1, -1, 2 * l, 2 * l);
        k_gemmP<<<NCTA, 256, GM_SMEM>>>(1, 1, g1 + l * DD, b1 + l * DD,
                                        2 * l, 2 * l + 1, 2 * l + 1);
    }

    k_nodeemb<<<(NN * 32 + 255) / 256, 256>>>(out, g2 + 2 * DD, b2 + 2 * DD);
    k_gsum<<<(NN + 255) / 256, 128>>>(out, bt);
    k_gemb<<<NG, DD>>>(out);
}